// round 1
// baseline (speedup 1.0000x reference)
#include <cuda_runtime.h>
#include <math.h>

#define B_    4
#define N_    2048
#define H_    16
#define DH    64
#define DM    1024
#define M_TOT (B_ * N_)        // 8192
#define QKV_N (3 * DM)         // 3072

// Scratch (static device globals — allocation-free per harness rules)
__device__ float g_q [(size_t)B_ * H_ * N_ * DH];   // [B,H,N,Dh] normalized q
__device__ float g_k [(size_t)B_ * H_ * N_ * DH];   // [B,H,N,Dh] normalized k
__device__ float g_v [(size_t)B_ * H_ * N_ * DH];   // [B,H,N,Dh] v
__device__ float g_ao[(size_t)B_ * N_ * H_ * DH];   // [B,N,H,Dh] attention output

// ---------------------------------------------------------------------------
// Kernel 1: QKV GEMM.  C[m,n] = sum_k X[m,k] * Wqkv[n,k] + bias[n]
// 128x128 tile, BK=16, 256 threads, 8x8 micro-tile. Epilogue scatters into
// g_q/g_k/g_v with layout [B,H,N,Dh].
// ---------------------------------------------------------------------------
__global__ __launch_bounds__(256) void qkv_gemm_kernel(
    const float* __restrict__ X,
    const float* __restrict__ W,
    const float* __restrict__ bias)
{
    __shared__ float As[16][132];
    __shared__ float Bs[16][132];

    const int n0  = blockIdx.x * 128;
    const int m0  = blockIdx.y * 128;
    const int tid = threadIdx.x;
    const int tx  = tid & 15;
    const int ty  = tid >> 4;
    const int lr  = tid >> 2;          // 0..63
    const int lc  = (tid & 3) << 2;    // 0,4,8,12

    float acc[8][8];
#pragma unroll
    for (int i = 0; i < 8; i++)
#pragma unroll
        for (int j = 0; j < 8; j++) acc[i][j] = 0.f;

    const float* Xp = X + (size_t)(m0 + lr) * DM + lc;
    const float* Wp = W + (size_t)(n0 + lr) * DM + lc;

    for (int k0 = 0; k0 < DM; k0 += 16) {
#pragma unroll
        for (int rr = 0; rr < 2; rr++) {
            float4 a = *(const float4*)(Xp + (size_t)rr * 64 * DM + k0);
            int r = lr + rr * 64;
            As[lc + 0][r] = a.x; As[lc + 1][r] = a.y;
            As[lc + 2][r] = a.z; As[lc + 3][r] = a.w;
            float4 b = *(const float4*)(Wp + (size_t)rr * 64 * DM + k0);
            Bs[lc + 0][r] = b.x; Bs[lc + 1][r] = b.y;
            Bs[lc + 2][r] = b.z; Bs[lc + 3][r] = b.w;
        }
        __syncthreads();
#pragma unroll
        for (int kk = 0; kk < 16; kk++) {
            float a[8], bb[8];
            *(float4*)&a [0] = *(const float4*)&As[kk][ty * 8];
            *(float4*)&a [4] = *(const float4*)&As[kk][ty * 8 + 4];
            *(float4*)&bb[0] = *(const float4*)&Bs[kk][tx * 8];
            *(float4*)&bb[4] = *(const float4*)&Bs[kk][tx * 8 + 4];
#pragma unroll
            for (int i = 0; i < 8; i++)
#pragma unroll
                for (int j = 0; j < 8; j++) acc[i][j] += a[i] * bb[j];
        }
        __syncthreads();
    }

    // Epilogue: add bias, scatter to q/k/v [B,H,N,Dh]
    const int nb    = n0 + tx * 8;          // 8 consecutive cols, same head
    const int which = nb >> 10;             // 0=q,1=k,2=v
    const int rem   = nb & 1023;
    const int h     = rem >> 6;
    const int d     = rem & 63;
    float* dst = (which == 0) ? g_q : ((which == 1) ? g_k : g_v);

    float bia[8];
#pragma unroll
    for (int j = 0; j < 8; j++) bia[j] = bias[nb + j];

#pragma unroll
    for (int i = 0; i < 8; i++) {
        int m  = m0 + ty * 8 + i;
        int b  = m >> 11;                   // / 2048
        int nt = m & 2047;
        float* p = dst + ((size_t)(b * H_ + h) * N_ + nt) * DH + d;
        float4 v0 = make_float4(acc[i][0] + bia[0], acc[i][1] + bia[1],
                                acc[i][2] + bia[2], acc[i][3] + bia[3]);
        float4 v1 = make_float4(acc[i][4] + bia[4], acc[i][5] + bia[5],
                                acc[i][6] + bia[6], acc[i][7] + bia[7]);
        *(float4*)(p)     = v0;
        *(float4*)(p + 4) = v1;
    }
}

// ---------------------------------------------------------------------------
// Kernel 2: L2 normalize rows of 64 (one warp per row). which: 0 -> q, 1 -> k
// ---------------------------------------------------------------------------
__global__ __launch_bounds__(256) void l2norm_kernel(int which)
{
    float* buf = which ? g_k : g_q;
    const int warp = (blockIdx.x * blockDim.x + threadIdx.x) >> 5;
    const int lane = threadIdx.x & 31;
    const int nrows = B_ * H_ * N_;
    if (warp >= nrows) return;
    float* row = buf + (size_t)warp * DH;
    float v0 = row[lane], v1 = row[lane + 32];
    float ss = v0 * v0 + v1 * v1;
#pragma unroll
    for (int off = 16; off >= 1; off >>= 1)
        ss += __shfl_xor_sync(0xffffffffu, ss, off);
    float inv = 1.f / fmaxf(sqrtf(ss), 1e-12f);
    row[lane]      = v0 * inv;
    row[lane + 32] = v1 * inv;
}

// ---------------------------------------------------------------------------
// Kernel 3: flash attention. Block = 64 query rows, loop over 64-key tiles.
// 256 threads as 16x16, 4x4 micro-tiles. Col mapping col = tx + 16*j.
// smem: Qs[64][68], Ks[64][68] (reused as Ps), Vs[64][68] -> 52224 B dynamic.
// ---------------------------------------------------------------------------
__global__ __launch_bounds__(256) void attn_kernel(const float* __restrict__ logit_scale)
{
    extern __shared__ float smempool[];
    float* Qs = smempool;              // [64][68]
    float* Ks = smempool + 64 * 68;    // [64][68]  (also Ps)
    float* Vs = smempool + 2 * 64 * 68;

    const int bh  = blockIdx.y;        // b*16 + h
    const int b   = bh >> 4;
    const int h   = bh & 15;
    const int q0  = blockIdx.x * 64;
    const int tid = threadIdx.x;
    const int tx  = tid & 15;
    const int ty  = tid >> 4;

    const float scale = __expf(fminf(logit_scale[h], 4.6051702f)); // log(100)

    const float* qbase = g_q + (size_t)bh * N_ * DH;
    const float* kbase = g_k + (size_t)bh * N_ * DH;
    const float* vbase = g_v + (size_t)bh * N_ * DH;

    // load Q tile [64][64]
    {
        int r  = tid >> 2;
        int c0 = (tid & 3) * 16;
        const float* src = qbase + (size_t)(q0 + r) * DH + c0;
#pragma unroll
        for (int cc = 0; cc < 16; cc += 4)
            *(float4*)&Qs[r * 68 + c0 + cc] = *(const float4*)(src + cc);
    }

    float m_[4], l_[4], o[4][4];
#pragma unroll
    for (int i = 0; i < 4; i++) {
        m_[i] = -INFINITY; l_[i] = 0.f;
#pragma unroll
        for (int j = 0; j < 4; j++) o[i][j] = 0.f;
    }

    for (int j0 = 0; j0 < N_; j0 += 64) {
        // load K,V tiles
        {
            int r  = tid >> 2;
            int c0 = (tid & 3) * 16;
            const float* ks = kbase + (size_t)(j0 + r) * DH + c0;
            const float* vs = vbase + (size_t)(j0 + r) * DH + c0;
#pragma unroll
            for (int cc = 0; cc < 16; cc += 4) {
                *(float4*)&Ks[r * 68 + c0 + cc] = *(const float4*)(ks + cc);
                *(float4*)&Vs[r * 68 + c0 + cc] = *(const float4*)(vs + cc);
            }
        }
        __syncthreads();

        // S = Q K^T
        float s[4][4];
#pragma unroll
        for (int i = 0; i < 4; i++)
#pragma unroll
            for (int j = 0; j < 4; j++) s[i][j] = 0.f;

        for (int kk = 0; kk < 64; kk++) {
            float a[4], bb[4];
#pragma unroll
            for (int i = 0; i < 4; i++) a[i] = Qs[(ty * 4 + i) * 68 + kk];
#pragma unroll
            for (int j = 0; j < 4; j++) bb[j] = Ks[(tx + 16 * j) * 68 + kk];
#pragma unroll
            for (int i = 0; i < 4; i++)
#pragma unroll
                for (int j = 0; j < 4; j++) s[i][j] += a[i] * bb[j];
        }
        __syncthreads();   // everyone done reading Ks before it becomes Ps

        // online softmax + write P into Ks(=Ps)
#pragma unroll
        for (int i = 0; i < 4; i++) {
            float mx = -INFINITY;
#pragma unroll
            for (int j = 0; j < 4; j++) { s[i][j] *= scale; mx = fmaxf(mx, s[i][j]); }
#pragma unroll
            for (int off = 8; off >= 1; off >>= 1)
                mx = fmaxf(mx, __shfl_xor_sync(0xffffffffu, mx, off));
            float mnew = fmaxf(m_[i], mx);
            float corr = __expf(m_[i] - mnew);
            float rs = 0.f;
#pragma unroll
            for (int j = 0; j < 4; j++) {
                float p = __expf(s[i][j] - mnew);
                s[i][j] = p; rs += p;
            }
#pragma unroll
            for (int off = 8; off >= 1; off >>= 1)
                rs += __shfl_xor_sync(0xffffffffu, rs, off);
            l_[i] = l_[i] * corr + rs;
            m_[i] = mnew;
#pragma unroll
            for (int jd = 0; jd < 4; jd++) o[i][jd] *= corr;
#pragma unroll
            for (int j = 0; j < 4; j++)
                Ks[(ty * 4 + i) * 68 + tx + 16 * j] = s[i][j];
        }
        __syncthreads();

        // O += P V
        for (int kn = 0; kn < 64; kn++) {
            float a[4], bv[4];
#pragma unroll
            for (int i = 0; i < 4; i++) a[i] = Ks[(ty * 4 + i) * 68 + kn];
#pragma unroll
            for (int jd = 0; jd < 4; jd++) bv[jd] = Vs[kn * 68 + tx + 16 * jd];
#pragma unroll
            for (int i = 0; i < 4; i++)
#pragma unroll
                for (int jd = 0; jd < 4; jd++) o[i][jd] += a[i] * bv[jd];
        }
        __syncthreads();
    }

    // finalize and write [B,N,H,Dh]
#pragma unroll
    for (int i = 0; i < 4; i++) {
        float inv = 1.f / l_[i];
        int n = q0 + ty * 4 + i;
        float* dst = g_ao + ((size_t)(b * N_ + n) * H_ + h) * DH;
#pragma unroll
        for (int jd = 0; jd < 4; jd++)
            dst[tx + 16 * jd] = o[i][jd] * inv;
    }
}

// ---------------------------------------------------------------------------
// Kernel 4: output projection.  out[m,n] = sum_k AO[m,k] * Wout[n,k]
// ---------------------------------------------------------------------------
__global__ __launch_bounds__(256) void out_gemm_kernel(
    const float* __restrict__ W,
    float* __restrict__ out)
{
    __shared__ float As[16][132];
    __shared__ float Bs[16][132];

    const int n0  = blockIdx.x * 128;
    const int m0  = blockIdx.y * 128;
    const int tid = threadIdx.x;
    const int tx  = tid & 15;
    const int ty  = tid >> 4;
    const int lr  = tid >> 2;
    const int lc  = (tid & 3) << 2;

    float acc[8][8];
#pragma unroll
    for (int i = 0; i < 8; i++)
#pragma unroll
        for (int j = 0; j < 8; j++) acc[i][j] = 0.f;

    const float* Xp = g_ao + (size_t)(m0 + lr) * DM + lc;
    const float* Wp = W    + (size_t)(n0 + lr) * DM + lc;

    for (int k0 = 0; k0 < DM; k0 += 16) {
#pragma unroll
        for (int rr = 0; rr < 2; rr++) {
            float4 a = *(const float4*)(Xp + (size_t)rr * 64 * DM + k0);
            int r = lr + rr * 64;
            As[lc + 0][r] = a.x; As[lc + 1][r] = a.y;
            As[lc + 2][r] = a.z; As[lc + 3][r] = a.w;
            float4 b = *(const float4*)(Wp + (size_t)rr * 64 * DM + k0);
            Bs[lc + 0][r] = b.x; Bs[lc + 1][r] = b.y;
            Bs[lc + 2][r] = b.z; Bs[lc + 3][r] = b.w;
        }
        __syncthreads();
#pragma unroll
        for (int kk = 0; kk < 16; kk++) {
            float a[8], bb[8];
            *(float4*)&a [0] = *(const float4*)&As[kk][ty * 8];
            *(float4*)&a [4] = *(const float4*)&As[kk][ty * 8 + 4];
            *(float4*)&bb[0] = *(const float4*)&Bs[kk][tx * 8];
            *(float4*)&bb[4] = *(const float4*)&Bs[kk][tx * 8 + 4];
#pragma unroll
            for (int i = 0; i < 8; i++)
#pragma unroll
                for (int j = 0; j < 8; j++) acc[i][j] += a[i] * bb[j];
        }
        __syncthreads();
    }

#pragma unroll
    for (int i = 0; i < 8; i++) {
        int m = m0 + ty * 8 + i;
        float* p = out + (size_t)m * DM + n0 + tx * 8;
        *(float4*)(p)     = make_float4(acc[i][0], acc[i][1], acc[i][2], acc[i][3]);
        *(float4*)(p + 4) = make_float4(acc[i][4], acc[i][5], acc[i][6], acc[i][7]);
    }
}

// ---------------------------------------------------------------------------
extern "C" void kernel_launch(void* const* d_in, const int* in_sizes, int n_in,
                              void* d_out, int out_size)
{
    const float* x       = (const float*)d_in[0];
    const float* w_qkv   = (const float*)d_in[1];
    const float* b_qkv   = (const float*)d_in[2];
    const float* w_out   = (const float*)d_in[3];
    const float* lscale  = (const float*)d_in[4];
    float* out = (float*)d_out;

    // 1. QKV projection + scatter
    dim3 g1(QKV_N / 128, M_TOT / 128);     // (24, 64)
    qkv_gemm_kernel<<<g1, 256>>>(x, w_qkv, b_qkv);

    // 2. L2 normalize q and k (warp per row; 8 warps per block)
    const int nrows = B_ * H_ * N_;        // 131072
    l2norm_kernel<<<nrows / 8, 256>>>(0);
    l2norm_kernel<<<nrows / 8, 256>>>(1);

    // 3. flash attention
    static const int ATTN_SMEM = 3 * 64 * 68 * (int)sizeof(float);  // 52224
    cudaFuncSetAttribute(attn_kernel, cudaFuncAttributeMaxDynamicSharedMemorySize, ATTN_SMEM);
    dim3 g3(N_ / 64, B_ * H_);             // (32, 64)
    attn_kernel<<<g3, 256, ATTN_SMEM>>>(lscale);

    // 4. output projection
    dim3 g4(DM / 128, M_TOT / 128);        // (8, 64)
    out_gemm_kernel<<<g4, 256>>>(w_out, out);
}

// round 3
// speedup vs baseline: 2.1340x; 2.1340x over previous
#include <cuda_runtime.h>
#include <cuda_bf16.h>
#include <math.h>
#include <stdint.h>

#define B_    4
#define N_    2048
#define H_    16
#define DH    64
#define DM    1024
#define M_TOT (B_ * N_)        // 8192
#define QKV_N (3 * DM)         // 3072
#define NROWS (B_ * H_ * N_)   // 131072

typedef __nv_bfloat16 bf16;

// ---------------------------------------------------------------------------
// Scratch (static device globals — allocation-free per harness rules)
// ---------------------------------------------------------------------------
__device__ float g_q [(size_t)NROWS * DH];          // [B,H,N,Dh] raw q (pre-norm)
__device__ float g_k [(size_t)NROWS * DH];          // [B,H,N,Dh] raw k

__device__ bf16 g_qh[(size_t)NROWS * DH];           // normalized*scale q hi/lo
__device__ bf16 g_ql[(size_t)NROWS * DH];
__device__ bf16 g_kh[(size_t)NROWS * DH];           // normalized k hi/lo
__device__ bf16 g_kl[(size_t)NROWS * DH];
__device__ bf16 g_vh[(size_t)NROWS * DH];           // v hi/lo ([B,H,N,Dh])
__device__ bf16 g_vl[(size_t)NROWS * DH];

__device__ bf16 g_x_hi [(size_t)M_TOT * DM];
__device__ bf16 g_x_lo [(size_t)M_TOT * DM];
__device__ bf16 g_wq_hi[(size_t)QKV_N * DM];
__device__ bf16 g_wq_lo[(size_t)QKV_N * DM];
__device__ bf16 g_wo_hi[(size_t)DM * DM];
__device__ bf16 g_wo_lo[(size_t)DM * DM];
__device__ bf16 g_aoh[(size_t)M_TOT * DM];          // attention out hi/lo [B*N, DM]
__device__ bf16 g_aol[(size_t)M_TOT * DM];

// ---------------------------------------------------------------------------
// mma.sync helpers (sm_80-era PTX — compiles for compute_103)
// ---------------------------------------------------------------------------
__device__ __forceinline__ void mma_bf16(float* c, const uint32_t* a,
                                         uint32_t b0, uint32_t b1) {
    asm volatile(
        "mma.sync.aligned.m16n8k16.row.col.f32.bf16.bf16.f32 "
        "{%0,%1,%2,%3}, {%4,%5,%6,%7}, {%8,%9}, {%0,%1,%2,%3};\n"
        : "+f"(c[0]), "+f"(c[1]), "+f"(c[2]), "+f"(c[3])
        : "r"(a[0]), "r"(a[1]), "r"(a[2]), "r"(a[3]), "r"(b0), "r"(b1));
}
__device__ __forceinline__ uint32_t pack_bf16(float x, float y) {
    __nv_bfloat162 t = __floats2bfloat162_rn(x, y);   // low = x, high = y
    return *(uint32_t*)&t;
}
__device__ __forceinline__ float bf16_round(float x) {
    return __bfloat162float(__float2bfloat16_rn(x));
}

// padded row stride (halfwords) for conflict-free fragment loads
#define LDK 72

// ---------------------------------------------------------------------------
// f32 -> (bf16 hi, bf16 lo).  4 elems / thread.
// ---------------------------------------------------------------------------
__global__ __launch_bounds__(256) void decomp_kernel(
    const float* __restrict__ src, bf16* __restrict__ hi, bf16* __restrict__ lo)
{
    size_t i = ((size_t)blockIdx.x * 256 + threadIdx.x) * 4;
    float4 v = *(const float4*)(src + i);
    float h0 = bf16_round(v.x), h1 = bf16_round(v.y);
    float h2 = bf16_round(v.z), h3 = bf16_round(v.w);
    *(uint32_t*)(hi + i)     = pack_bf16(v.x, v.y);
    *(uint32_t*)(hi + i + 2) = pack_bf16(v.z, v.w);
    *(uint32_t*)(lo + i)     = pack_bf16(v.x - h0, v.y - h1);
    *(uint32_t*)(lo + i + 2) = pack_bf16(v.z - h2, v.w - h3);
}

// ---------------------------------------------------------------------------
// EC bf16 GEMM via mma.sync:  C[m,n] = sum_k A[m,k]*B[n,k]  (+bias, scatter)
// Block 128x128, 256 thr (8 warps as 4x2), warp tile 32x64, K-chunk 64.
// mode 0: QKV epilogue (bias; q,k -> float g_q/g_k; v -> bf16 hi/lo g_vh/g_vl)
// mode 1: row-major float store to Cout [M,1024]
// ---------------------------------------------------------------------------
#define GS_AH 0
#define GS_AL (GS_AH + 128 * LDK * 2)
#define GS_BH (GS_AL + 128 * LDK * 2)
#define GS_BL (GS_BH + 128 * LDK * 2)
#define GS_TOTAL (GS_BL + 128 * LDK * 2)   // 73728 B

__global__ __launch_bounds__(256) void gemm_mma_kernel(
    const bf16* __restrict__ Ahi, const bf16* __restrict__ Alo,
    const bf16* __restrict__ Bhi, const bf16* __restrict__ Blo,
    const float* __restrict__ bias, float* __restrict__ Cout, int mode)
{
    extern __shared__ char smem[];
    const int tid  = threadIdx.x;
    const int wid  = tid >> 5;
    const int lane = tid & 31;
    const int wm   = wid & 3;          // m quadrant (32 rows)
    const int wn   = wid >> 2;         // n half (64 cols)
    const int qd   = lane & 3;
    const int r4   = lane >> 2;
    const int m0 = blockIdx.y * 128;
    const int n0 = blockIdx.x * 128;

    float c[2][8][4];
#pragma unroll
    for (int mt = 0; mt < 2; mt++)
#pragma unroll
        for (int nt = 0; nt < 8; nt++)
#pragma unroll
            for (int j = 0; j < 4; j++) c[mt][nt][j] = 0.f;

    const int row  = tid >> 1;         // 0..127
    const int half = tid & 1;          // 32-elem half of the 64-col chunk

    for (int ch = 0; ch < 16; ch++) {
        // ---- load chunk (A rows m0+row, B rows n0+row; cols [64ch,64ch+64)) ----
        {
            const size_t aoff = ((size_t)(m0 + row) * DM + ch * 64 + half * 32) * 2;
            const size_t boff = ((size_t)(n0 + row) * DM + ch * 64 + half * 32) * 2;
            char* sA = smem + (row * LDK + half * 32) * 2;
#pragma unroll
            for (int i = 0; i < 4; i++) {
                *(uint4*)(sA + GS_AH + i * 16) = *(const uint4*)((const char*)Ahi + aoff + i * 16);
                *(uint4*)(sA + GS_AL + i * 16) = *(const uint4*)((const char*)Alo + aoff + i * 16);
                *(uint4*)(sA + GS_BH + i * 16) = *(const uint4*)((const char*)Bhi + boff + i * 16);
                *(uint4*)(sA + GS_BL + i * 16) = *(const uint4*)((const char*)Blo + boff + i * 16);
            }
        }
        __syncthreads();

#pragma unroll
        for (int ks = 0; ks < 4; ks++) {
            uint32_t ah[2][4], al[2][4];
#pragma unroll
            for (int mt = 0; mt < 2; mt++) {
                int base = (wm * 32 + mt * 16 + r4) * LDK + ks * 16 + qd * 2;
                ah[mt][0] = *(uint32_t*)(smem + GS_AH + base * 2);
                ah[mt][1] = *(uint32_t*)(smem + GS_AH + (base + 8 * LDK) * 2);
                ah[mt][2] = *(uint32_t*)(smem + GS_AH + (base + 8) * 2);
                ah[mt][3] = *(uint32_t*)(smem + GS_AH + (base + 8 * LDK + 8) * 2);
                al[mt][0] = *(uint32_t*)(smem + GS_AL + base * 2);
                al[mt][1] = *(uint32_t*)(smem + GS_AL + (base + 8 * LDK) * 2);
                al[mt][2] = *(uint32_t*)(smem + GS_AL + (base + 8) * 2);
                al[mt][3] = *(uint32_t*)(smem + GS_AL + (base + 8 * LDK + 8) * 2);
            }
#pragma unroll
            for (int nt = 0; nt < 8; nt++) {
                int base = (wn * 64 + nt * 8 + r4) * LDK + ks * 16 + qd * 2;
                uint32_t bh0 = *(uint32_t*)(smem + GS_BH + base * 2);
                uint32_t bh1 = *(uint32_t*)(smem + GS_BH + (base + 8) * 2);
                uint32_t bl0 = *(uint32_t*)(smem + GS_BL + base * 2);
                uint32_t bl1 = *(uint32_t*)(smem + GS_BL + (base + 8) * 2);
#pragma unroll
                for (int mt = 0; mt < 2; mt++) {
                    mma_bf16(c[mt][nt], ah[mt], bh0, bh1);
                    mma_bf16(c[mt][nt], ah[mt], bl0, bl1);
                    mma_bf16(c[mt][nt], al[mt], bh0, bh1);
                }
            }
        }
        __syncthreads();
    }

    // ---- epilogue ----
#pragma unroll
    for (int nt = 0; nt < 8; nt++) {
        const int nb = n0 + wn * 64 + nt * 8 + qd * 2;
        if (mode == 0) {
            const int which = nb >> 10;
            const int rem   = nb & 1023;
            const int hh    = rem >> 6;
            const int d     = rem & 63;
            const float b0 = bias[nb], b1 = bias[nb + 1];
#pragma unroll
            for (int mt = 0; mt < 2; mt++) {
#pragma unroll
                for (int rr = 0; rr < 2; rr++) {
                    const int m = m0 + wm * 32 + mt * 16 + r4 + rr * 8;
                    const int bidx = m >> 11, ntok = m & 2047;
                    const size_t sidx = ((size_t)(bidx * H_ + hh) * N_ + ntok) * DH + d;
                    float f0 = c[mt][nt][rr * 2 + 0] + b0;
                    float f1 = c[mt][nt][rr * 2 + 1] + b1;
                    if (which == 0)      *(float2*)(g_q + sidx) = make_float2(f0, f1);
                    else if (which == 1) *(float2*)(g_k + sidx) = make_float2(f0, f1);
                    else {
                        *(uint32_t*)(g_vh + sidx) = pack_bf16(f0, f1);
                        *(uint32_t*)(g_vl + sidx) = pack_bf16(f0 - bf16_round(f0),
                                                              f1 - bf16_round(f1));
                    }
                }
            }
        } else {
#pragma unroll
            for (int mt = 0; mt < 2; mt++) {
#pragma unroll
                for (int rr = 0; rr < 2; rr++) {
                    const int m = m0 + wm * 32 + mt * 16 + r4 + rr * 8;
                    *(float2*)(Cout + (size_t)m * DM + nb) =
                        make_float2(c[mt][nt][rr * 2 + 0], c[mt][nt][rr * 2 + 1]);
                }
            }
        }
    }
}

// ---------------------------------------------------------------------------
// L2 normalize rows of 64 + bf16 hi/lo emit. which 0: q (scale folded), 1: k.
// One warp per row; lane handles elements 2l, 2l+1.
// ---------------------------------------------------------------------------
__global__ __launch_bounds__(256) void l2norm_kernel(const float* __restrict__ lscale,
                                                     int which)
{
    const int warp = (blockIdx.x * blockDim.x + threadIdx.x) >> 5;
    const int lane = threadIdx.x & 31;
    if (warp >= NROWS) return;
    const float* row = (which ? g_k : g_q) + (size_t)warp * DH;
    float2 v = *(const float2*)(row + 2 * lane);
    float ss = v.x * v.x + v.y * v.y;
#pragma unroll
    for (int off = 16; off >= 1; off >>= 1)
        ss += __shfl_xor_sync(0xffffffffu, ss, off);
    float sc = 1.f;
    if (which == 0) {
        const int h = (warp >> 11) & (H_ - 1);
        sc = __expf(fminf(lscale[h], 4.6051702f));
    }
    const float inv = sc / fmaxf(sqrtf(ss), 1e-12f);
    const float f0 = v.x * inv, f1 = v.y * inv;
    bf16* hi = which ? g_kh : g_qh;
    bf16* lo = which ? g_kl : g_ql;
    const size_t idx = (size_t)warp * DH + 2 * lane;
    *(uint32_t*)(hi + idx) = pack_bf16(f0, f1);
    *(uint32_t*)(lo + idx) = pack_bf16(f0 - bf16_round(f0), f1 - bf16_round(f1));
}

// ---------------------------------------------------------------------------
// Flash attention, EC bf16 mma.sync. CTA = 128 thr (4 warps), Q block 64
// (16 rows/warp), K tile 64. Scale pre-folded into q. Emits ao hi/lo.
// smem (bytes): Qh,Ql,Kh,Kl,Vth,Vtl each 64*LDK*2 = 9216 -> 55296 total.
// ---------------------------------------------------------------------------
#define AS_QH 0
#define AS_QL (AS_QH + 64 * LDK * 2)
#define AS_KH (AS_QL + 64 * LDK * 2)
#define AS_KL (AS_KH + 64 * LDK * 2)
#define AS_VH (AS_KL + 64 * LDK * 2)
#define AS_VL (AS_VH + 64 * LDK * 2)
#define AS_TOTAL (AS_VL + 64 * LDK * 2)  // 55296

__global__ __launch_bounds__(128) void attn_mma_kernel()
{
    extern __shared__ char smem[];
    const int tid  = threadIdx.x;
    const int wid  = tid >> 5;
    const int lane = tid & 31;
    const int qd   = lane & 3;
    const int r4   = lane >> 2;
    const int bh = blockIdx.y;
    const int b  = bh >> 4;
    const int h  = bh & 15;
    const int q0 = blockIdx.x * 64;

    const size_t rowbase = (size_t)bh * N_ * DH;

    // ---- load Q tile (scaled, normalized, hi/lo) ----
    {
        const int row = tid >> 1, half = tid & 1;
        const size_t off = (rowbase + (size_t)(q0 + row) * DH + half * 32) * 2;
        char* s = smem + (row * LDK + half * 32) * 2;
#pragma unroll
        for (int i = 0; i < 4; i++) {
            *(uint4*)(s + AS_QH + i * 16) = *(const uint4*)((const char*)g_qh + off + i * 16);
            *(uint4*)(s + AS_QL + i * 16) = *(const uint4*)((const char*)g_ql + off + i * 16);
        }
    }

    float o[8][4];
#pragma unroll
    for (int dn = 0; dn < 8; dn++)
#pragma unroll
        for (int j = 0; j < 4; j++) o[dn][j] = 0.f;
    float mrow0 = -INFINITY, mrow1 = -INFINITY, lrow0 = 0.f, lrow1 = 0.f;

    for (int j0 = 0; j0 < N_; j0 += 64) {
        // ---- load K tile (rows) ----
        {
            const int row = tid >> 1, half = tid & 1;
            const size_t off = (rowbase + (size_t)(j0 + row) * DH + half * 32) * 2;
            char* s = smem + (row * LDK + half * 32) * 2;
#pragma unroll
            for (int i = 0; i < 4; i++) {
                *(uint4*)(s + AS_KH + i * 16) = *(const uint4*)((const char*)g_kh + off + i * 16);
                *(uint4*)(s + AS_KL + i * 16) = *(const uint4*)((const char*)g_kl + off + i * 16);
            }
        }
        // ---- load V tile transposed: Vt[d][j], j pairs packed in u32 ----
        {
            const int jp = tid & 31, dq = tid >> 5;        // dq in 0..3 -> 16 d vals
            const size_t o0 = rowbase + (size_t)(j0 + 2 * jp) * DH + dq * 16;
            uint32_t uah[8], ubh[8], ual[8], ubl[8];
            *(uint4*)(uah)     = *(const uint4*)(g_vh + o0);
            *(uint4*)(uah + 4) = *(const uint4*)(g_vh + o0 + 8);
            *(uint4*)(ubh)     = *(const uint4*)(g_vh + o0 + DH);
            *(uint4*)(ubh + 4) = *(const uint4*)(g_vh + o0 + DH + 8);
            *(uint4*)(ual)     = *(const uint4*)(g_vl + o0);
            *(uint4*)(ual + 4) = *(const uint4*)(g_vl + o0 + 8);
            *(uint4*)(ubl)     = *(const uint4*)(g_vl + o0 + DH);
            *(uint4*)(ubl + 4) = *(const uint4*)(g_vl + o0 + DH + 8);
#pragma unroll
            for (int t = 0; t < 8; t++) {
                const int d0 = dq * 16 + 2 * t;
                uint32_t w0h = (uah[t] & 0xffffu) | (ubh[t] << 16);
                uint32_t w1h = (uah[t] >> 16)     | (ubh[t] & 0xffff0000u);
                uint32_t w0l = (ual[t] & 0xffffu) | (ubl[t] << 16);
                uint32_t w1l = (ual[t] >> 16)     | (ubl[t] & 0xffff0000u);
                *(uint32_t*)(smem + AS_VH + (d0 * LDK + 2 * jp) * 2)       = w0h;
                *(uint32_t*)(smem + AS_VH + ((d0 + 1) * LDK + 2 * jp) * 2) = w1h;
                *(uint32_t*)(smem + AS_VL + (d0 * LDK + 2 * jp) * 2)       = w0l;
                *(uint32_t*)(smem + AS_VL + ((d0 + 1) * LDK + 2 * jp) * 2) = w1l;
            }
        }
        __syncthreads();

        // ---- S = Q K^T (EC, 3 passes) ----
        float s[8][4];
#pragma unroll
        for (int nt = 0; nt < 8; nt++)
#pragma unroll
            for (int j = 0; j < 4; j++) s[nt][j] = 0.f;

#pragma unroll
        for (int ks = 0; ks < 4; ks++) {
            uint32_t aqh[4], aql[4];
            {
                const int base = (wid * 16 + r4) * LDK + ks * 16 + qd * 2;
                aqh[0] = *(uint32_t*)(smem + AS_QH + base * 2);
                aqh[1] = *(uint32_t*)(smem + AS_QH + (base + 8 * LDK) * 2);
                aqh[2] = *(uint32_t*)(smem + AS_QH + (base + 8) * 2);
                aqh[3] = *(uint32_t*)(smem + AS_QH + (base + 8 * LDK + 8) * 2);
                aql[0] = *(uint32_t*)(smem + AS_QL + base * 2);
                aql[1] = *(uint32_t*)(smem + AS_QL + (base + 8 * LDK) * 2);
                aql[2] = *(uint32_t*)(smem + AS_QL + (base + 8) * 2);
                aql[3] = *(uint32_t*)(smem + AS_QL + (base + 8 * LDK + 8) * 2);
            }
#pragma unroll
            for (int nt = 0; nt < 8; nt++) {
                const int base = (nt * 8 + r4) * LDK + ks * 16 + qd * 2;
                uint32_t bh0 = *(uint32_t*)(smem + AS_KH + base * 2);
                uint32_t bh1 = *(uint32_t*)(smem + AS_KH + (base + 8) * 2);
                uint32_t bl0 = *(uint32_t*)(smem + AS_KL + base * 2);
                uint32_t bl1 = *(uint32_t*)(smem + AS_KL + (base + 8) * 2);
                mma_bf16(s[nt], aqh, bh0, bh1);
                mma_bf16(s[nt], aqh, bl0, bl1);
                mma_bf16(s[nt], aql, bh0, bh1);
            }
        }

        // ---- online softmax (rows r4 / r4+8, replicated across quad) ----
        float mx0 = -INFINITY, mx1 = -INFINITY;
#pragma unroll
        for (int nt = 0; nt < 8; nt++) {
            mx0 = fmaxf(mx0, fmaxf(s[nt][0], s[nt][1]));
            mx1 = fmaxf(mx1, fmaxf(s[nt][2], s[nt][3]));
        }
        mx0 = fmaxf(mx0, __shfl_xor_sync(0xffffffffu, mx0, 1));
        mx0 = fmaxf(mx0, __shfl_xor_sync(0xffffffffu, mx0, 2));
        mx1 = fmaxf(mx1, __shfl_xor_sync(0xffffffffu, mx1, 1));
        mx1 = fmaxf(mx1, __shfl_xor_sync(0xffffffffu, mx1, 2));
        const float mnew0 = fmaxf(mrow0, mx0);
        const float mnew1 = fmaxf(mrow1, mx1);
        const float corr0 = __expf(mrow0 - mnew0);
        const float corr1 = __expf(mrow1 - mnew1);
        float rs0 = 0.f, rs1 = 0.f;
#pragma unroll
        for (int nt = 0; nt < 8; nt++) {
            s[nt][0] = __expf(s[nt][0] - mnew0);
            s[nt][1] = __expf(s[nt][1] - mnew0);
            s[nt][2] = __expf(s[nt][2] - mnew1);
            s[nt][3] = __expf(s[nt][3] - mnew1);
            rs0 += s[nt][0] + s[nt][1];
            rs1 += s[nt][2] + s[nt][3];
        }
        rs0 += __shfl_xor_sync(0xffffffffu, rs0, 1);
        rs0 += __shfl_xor_sync(0xffffffffu, rs0, 2);
        rs1 += __shfl_xor_sync(0xffffffffu, rs1, 1);
        rs1 += __shfl_xor_sync(0xffffffffu, rs1, 2);
        lrow0 = lrow0 * corr0 + rs0;
        lrow1 = lrow1 * corr1 + rs1;
        mrow0 = mnew0; mrow1 = mnew1;
#pragma unroll
        for (int dn = 0; dn < 8; dn++) {
            o[dn][0] *= corr0; o[dn][1] *= corr0;
            o[dn][2] *= corr1; o[dn][3] *= corr1;
        }

        // ---- O += P V (EC, P frags repacked from S frags) ----
#pragma unroll
        for (int kt = 0; kt < 4; kt++) {
            const int u = 2 * kt, v2 = 2 * kt + 1;
            uint32_t pah[4], pal[4];
            pah[0] = pack_bf16(s[u][0],  s[u][1]);
            pah[1] = pack_bf16(s[u][2],  s[u][3]);
            pah[2] = pack_bf16(s[v2][0], s[v2][1]);
            pah[3] = pack_bf16(s[v2][2], s[v2][3]);
            pal[0] = pack_bf16(s[u][0]  - bf16_round(s[u][0]),  s[u][1]  - bf16_round(s[u][1]));
            pal[1] = pack_bf16(s[u][2]  - bf16_round(s[u][2]),  s[u][3]  - bf16_round(s[u][3]));
            pal[2] = pack_bf16(s[v2][0] - bf16_round(s[v2][0]), s[v2][1] - bf16_round(s[v2][1]));
            pal[3] = pack_bf16(s[v2][2] - bf16_round(s[v2][2]), s[v2][3] - bf16_round(s[v2][3]));
#pragma unroll
            for (int dn = 0; dn < 8; dn++) {
                const int base = (dn * 8 + r4) * LDK + kt * 16 + qd * 2;
                uint32_t vh0 = *(uint32_t*)(smem + AS_VH + base * 2);
                uint32_t vh1 = *(uint32_t*)(smem + AS_VH + (base + 8) * 2);
                uint32_t vl0 = *(uint32_t*)(smem + AS_VL + base * 2);
                uint32_t vl1 = *(uint32_t*)(smem + AS_VL + (base + 8) * 2);
                mma_bf16(o[dn], pah, vh0, vh1);
                mma_bf16(o[dn], pah, vl0, vl1);
                mma_bf16(o[dn], pal, vh0, vh1);
            }
        }
        __syncthreads();
    }

    // ---- finalize: write ao hi/lo at [b*N+n][h*64+d] ----
    const float inv0 = 1.f / lrow0;
    const float inv1 = 1.f / lrow1;
#pragma unroll
    for (int dn = 0; dn < 8; dn++) {
        const int d = dn * 8 + qd * 2;
#pragma unroll
        for (int rr = 0; rr < 2; rr++) {
            const int n = q0 + wid * 16 + r4 + rr * 8;
            const float inv = rr ? inv1 : inv0;
            const float f0 = o[dn][rr * 2 + 0] * inv;
            const float f1 = o[dn][rr * 2 + 1] * inv;
            const size_t idx = (size_t)(b * N_ + n) * DM + h * 64 + d;
            *(uint32_t*)(g_aoh + idx) = pack_bf16(f0, f1);
            *(uint32_t*)(g_aol + idx) = pack_bf16(f0 - bf16_round(f0), f1 - bf16_round(f1));
        }
    }
}

// ---------------------------------------------------------------------------
extern "C" void kernel_launch(void* const* d_in, const int* in_sizes, int n_in,
                              void* d_out, int out_size)
{
    const float* x      = (const float*)d_in[0];
    const float* w_qkv  = (const float*)d_in[1];
    const float* b_qkv  = (const float*)d_in[2];
    const float* w_out  = (const float*)d_in[3];
    const float* lscale = (const float*)d_in[4];
    float* out = (float*)d_out;

    bf16 *xh, *xl, *wqh, *wql, *woh, *wol, *aoh, *aol;
    cudaGetSymbolAddress((void**)&xh,  g_x_hi);
    cudaGetSymbolAddress((void**)&xl,  g_x_lo);
    cudaGetSymbolAddress((void**)&wqh, g_wq_hi);
    cudaGetSymbolAddress((void**)&wql, g_wq_lo);
    cudaGetSymbolAddress((void**)&woh, g_wo_hi);
    cudaGetSymbolAddress((void**)&wol, g_wo_lo);
    cudaGetSymbolAddress((void**)&aoh, g_aoh);
    cudaGetSymbolAddress((void**)&aol, g_aol);

    cudaFuncSetAttribute(gemm_mma_kernel, cudaFuncAttributeMaxDynamicSharedMemorySize, GS_TOTAL);
    cudaFuncSetAttribute(attn_mma_kernel, cudaFuncAttributeMaxDynamicSharedMemorySize, AS_TOTAL);

    // 0. decompose inputs
    decomp_kernel<<<(M_TOT * DM) / 1024, 256>>>(x,     xh,  xl);
    decomp_kernel<<<(QKV_N * DM) / 1024, 256>>>(w_qkv, wqh, wql);
    decomp_kernel<<<(DM * DM)    / 1024, 256>>>(w_out, woh, wol);

    // 1. QKV projection: q,k -> float; v -> bf16 hi/lo directly
    dim3 g1(QKV_N / 128, M_TOT / 128);     // (24, 64)
    gemm_mma_kernel<<<g1, 256, GS_TOTAL>>>(xh, xl, wqh, wql, b_qkv, nullptr, 0);

    // 2. normalize q (scale folded) and k, emit hi/lo
    l2norm_kernel<<<NROWS / 8, 256>>>(lscale, 0);
    l2norm_kernel<<<NROWS / 8, 256>>>(lscale, 1);

    // 3. flash attention -> ao hi/lo
    dim3 g3(N_ / 64, B_ * H_);             // (32, 64)
    attn_mma_kernel<<<g3, 128, AS_TOTAL>>>();

    // 4. output projection -> d_out
    dim3 g4(DM / 128, M_TOT / 128);        // (8, 64)
    gemm_mma_kernel<<<g4, 256, GS_TOTAL>>>(aoh, aol, woh, wol, nullptr, out, 1);
}